// round 1
// baseline (speedup 1.0000x reference)
#include <cuda_runtime.h>
#include <math.h>

#define BB 16
#define TT 1024
#define CIN 512
#define NF 512
#define NH 4
#define DK 128
#define QKV_LD 1536
#define KER 11
#define LPAD 5
#define NEGV (-1.0e9f)
#define SCALE 0.08838834764831845f  // 128^-0.5

// Scratch (static device globals; no runtime allocation)
static __device__ float g_qkv[(size_t)BB * TT * QKV_LD];          // 100 MB
static __device__ float g_scores[(size_t)BB * NH * TT * TT];      // 256 MB
static __device__ float g_ctx[(size_t)BB * TT * NF];              // 33.5 MB
static __device__ float g_fsmn[(size_t)BB * TT * NF];             // 33.5 MB

// ---------------------------------------------------------------------------
// GEMM 1: qkv[M=16384, N=1536] = X[M,512] @ Wqkv[512,1536] + b_qkv
// ---------------------------------------------------------------------------
__global__ void k_gemm_qkv(const float* __restrict__ X,
                           const float* __restrict__ W,
                           const float* __restrict__ bias) {
    __shared__ float As[16][65];
    __shared__ float Bs[16][65];
    const int m0 = blockIdx.y * 64;
    const int n0 = blockIdx.x * 64;
    const int tid = threadIdx.x;
    const int tx = tid & 15, ty = tid >> 4;
    float acc[4][4];
#pragma unroll
    for (int i = 0; i < 4; i++)
#pragma unroll
        for (int j = 0; j < 4; j++) acc[i][j] = 0.f;

    for (int k0 = 0; k0 < CIN; k0 += 16) {
#pragma unroll
        for (int i = 0; i < 4; ++i) {          // A tile: kk fastest (coalesced)
            int e = tid + i * 256;
            int kk = e & 15, row = e >> 4;
            As[kk][row] = X[(size_t)(m0 + row) * CIN + k0 + kk];
        }
#pragma unroll
        for (int i = 0; i < 4; ++i) {          // B tile: col fastest (coalesced)
            int e = tid + i * 256;
            int col = e & 63, kk = e >> 6;
            Bs[kk][col] = W[(size_t)(k0 + kk) * QKV_LD + n0 + col];
        }
        __syncthreads();
#pragma unroll
        for (int kk = 0; kk < 16; ++kk) {
            float a[4], bv[4];
#pragma unroll
            for (int i = 0; i < 4; i++) a[i] = As[kk][ty * 4 + i];
#pragma unroll
            for (int j = 0; j < 4; j++) bv[j] = Bs[kk][tx * 4 + j];
#pragma unroll
            for (int i = 0; i < 4; i++)
#pragma unroll
                for (int j = 0; j < 4; j++) acc[i][j] += a[i] * bv[j];
        }
        __syncthreads();
    }
#pragma unroll
    for (int i = 0; i < 4; i++) {
        int m = m0 + ty * 4 + i;
#pragma unroll
        for (int j = 0; j < 4; j++) {
            int n = n0 + tx * 4 + j;
            g_qkv[(size_t)m * QKV_LD + n] = acc[i][j] + bias[n];
        }
    }
}

// ---------------------------------------------------------------------------
// FSMN: depthwise conv (k=11) over masked V + residual, re-masked.
// One block per (b,t), 512 threads = channels.
// ---------------------------------------------------------------------------
__global__ void k_fsmn(const float* __restrict__ mask,
                       const float* __restrict__ w_fsmn) {
    const int bt = blockIdx.x;
    const int b = bt >> 10;         // / TT
    const int t = bt & (TT - 1);
    const int d = threadIdx.x;
    const float m = mask[b * TT + t];
    const float* vbase = g_qkv + (size_t)b * TT * QKV_LD + 2 * NF + d;
    float acc = vbase[(size_t)t * QKV_LD] * m;   // residual (inp)
#pragma unroll
    for (int j = 0; j < KER; ++j) {
        int tt = t + j - LPAD;
        if (tt >= 0 && tt < TT) {
            float mm = mask[b * TT + tt];
            acc += w_fsmn[d * KER + j] * vbase[(size_t)tt * QKV_LD] * mm;
        }
    }
    g_fsmn[(size_t)bt * NF + d] = acc * m;
}

// ---------------------------------------------------------------------------
// GEMM 2: scores[b,h] = (Q*scale) @ K^T with key mask -> -1e9
// grid: (T/64, T/64, B*H)
// ---------------------------------------------------------------------------
__global__ void k_gemm_scores(const float* __restrict__ mask) {
    __shared__ float As[16][65];
    __shared__ float Bs[16][65];
    const int bh = blockIdx.z;
    const int b = bh >> 2, h = bh & 3;
    const float* Q = g_qkv + (size_t)b * TT * QKV_LD + h * DK;
    const float* Kp = g_qkv + (size_t)b * TT * QKV_LD + NF + h * DK;
    float* S = g_scores + (size_t)bh * TT * TT;

    const int m0 = blockIdx.y * 64;
    const int n0 = blockIdx.x * 64;
    const int tid = threadIdx.x;
    const int tx = tid & 15, ty = tid >> 4;
    float acc[4][4];
#pragma unroll
    for (int i = 0; i < 4; i++)
#pragma unroll
        for (int j = 0; j < 4; j++) acc[i][j] = 0.f;

    for (int k0 = 0; k0 < DK; k0 += 16) {
#pragma unroll
        for (int i = 0; i < 4; ++i) {          // Q: kk fastest
            int e = tid + i * 256;
            int kk = e & 15, row = e >> 4;
            As[kk][row] = Q[(size_t)(m0 + row) * QKV_LD + k0 + kk];
        }
#pragma unroll
        for (int i = 0; i < 4; ++i) {          // K (transposed access): kk fastest
            int e = tid + i * 256;
            int kk = e & 15, col = e >> 4;
            Bs[kk][col] = Kp[(size_t)(n0 + col) * QKV_LD + k0 + kk];
        }
        __syncthreads();
#pragma unroll
        for (int kk = 0; kk < 16; ++kk) {
            float a[4], bv[4];
#pragma unroll
            for (int i = 0; i < 4; i++) a[i] = As[kk][ty * 4 + i];
#pragma unroll
            for (int j = 0; j < 4; j++) bv[j] = Bs[kk][tx * 4 + j];
#pragma unroll
            for (int i = 0; i < 4; i++)
#pragma unroll
                for (int j = 0; j < 4; j++) acc[i][j] += a[i] * bv[j];
        }
        __syncthreads();
    }
#pragma unroll
    for (int j = 0; j < 4; j++) {
        int n = n0 + tx * 4 + j;
        float mv = mask[b * TT + n];
#pragma unroll
        for (int i = 0; i < 4; i++) {
            int m = m0 + ty * 4 + i;
            S[(size_t)m * TT + n] = (mv != 0.f) ? acc[i][j] * SCALE : NEGV;
        }
    }
}

// ---------------------------------------------------------------------------
// Row softmax over 1024 keys. One block (256 threads) per row.
// ---------------------------------------------------------------------------
__global__ void k_softmax() {
    float* S = g_scores + (size_t)blockIdx.x * TT;
    const int tid = threadIdx.x;
    float v[4];
    float mx = -INFINITY;
#pragma unroll
    for (int i = 0; i < 4; i++) {
        v[i] = S[tid + i * 256];
        mx = fmaxf(mx, v[i]);
    }
    __shared__ float shm[8], shs[8];
#pragma unroll
    for (int o = 16; o > 0; o >>= 1) mx = fmaxf(mx, __shfl_xor_sync(0xffffffffu, mx, o));
    if ((tid & 31) == 0) shm[tid >> 5] = mx;
    __syncthreads();
    if (tid == 0) {
        float t = shm[0];
        for (int w = 1; w < 8; w++) t = fmaxf(t, shm[w]);
        shm[0] = t;
    }
    __syncthreads();
    const float bm = shm[0];
    float s = 0.f;
#pragma unroll
    for (int i = 0; i < 4; i++) {
        v[i] = __expf(v[i] - bm);   // masked entries: exp(~-1e9) == 0 exactly
        s += v[i];
    }
#pragma unroll
    for (int o = 16; o > 0; o >>= 1) s += __shfl_xor_sync(0xffffffffu, s, o);
    if ((tid & 31) == 0) shs[tid >> 5] = s;
    __syncthreads();
    if (tid == 0) {
        float t = 0.f;
        for (int w = 0; w < 8; w++) t += shs[w];
        shs[0] = t;
    }
    __syncthreads();
    const float inv = 1.f / shs[0];
#pragma unroll
    for (int i = 0; i < 4; i++) S[tid + i * 256] = v[i] * inv;
}

// ---------------------------------------------------------------------------
// GEMM 3: ctx[b,h] = P[T,T] @ V[T,128];  grid (DK/64, T/64, B*H)
// ---------------------------------------------------------------------------
__global__ void k_gemm_pv() {
    __shared__ float As[16][65];
    __shared__ float Bs[16][65];
    const int bh = blockIdx.z;
    const int b = bh >> 2, h = bh & 3;
    const float* P = g_scores + (size_t)bh * TT * TT;
    const float* V = g_qkv + (size_t)b * TT * QKV_LD + 2 * NF + h * DK;

    const int m0 = blockIdx.y * 64;
    const int n0 = blockIdx.x * 64;
    const int tid = threadIdx.x;
    const int tx = tid & 15, ty = tid >> 4;
    float acc[4][4];
#pragma unroll
    for (int i = 0; i < 4; i++)
#pragma unroll
        for (int j = 0; j < 4; j++) acc[i][j] = 0.f;

    for (int k0 = 0; k0 < TT; k0 += 16) {
#pragma unroll
        for (int i = 0; i < 4; ++i) {          // P tile: kk fastest
            int e = tid + i * 256;
            int kk = e & 15, row = e >> 4;
            As[kk][row] = P[(size_t)(m0 + row) * TT + k0 + kk];
        }
#pragma unroll
        for (int i = 0; i < 4; ++i) {          // V tile: col fastest
            int e = tid + i * 256;
            int col = e & 63, kk = e >> 6;
            Bs[kk][col] = V[(size_t)(k0 + kk) * QKV_LD + n0 + col];
        }
        __syncthreads();
#pragma unroll
        for (int kk = 0; kk < 16; ++kk) {
            float a[4], bv[4];
#pragma unroll
            for (int i = 0; i < 4; i++) a[i] = As[kk][ty * 4 + i];
#pragma unroll
            for (int j = 0; j < 4; j++) bv[j] = Bs[kk][tx * 4 + j];
#pragma unroll
            for (int i = 0; i < 4; i++)
#pragma unroll
                for (int j = 0; j < 4; j++) acc[i][j] += a[i] * bv[j];
        }
        __syncthreads();
    }
#pragma unroll
    for (int i = 0; i < 4; i++) {
        int m = m0 + ty * 4 + i;
#pragma unroll
        for (int j = 0; j < 4; j++) {
            int n = n0 + tx * 4 + j;
            g_ctx[((size_t)b * TT + m) * NF + h * DK + n] = acc[i][j];
        }
    }
}

// ---------------------------------------------------------------------------
// GEMM 4: out = ctx @ w_out + b_out + fsmn
// ---------------------------------------------------------------------------
__global__ void k_gemm_out(const float* __restrict__ W,
                           const float* __restrict__ bias,
                           float* __restrict__ out) {
    __shared__ float As[16][65];
    __shared__ float Bs[16][65];
    const int m0 = blockIdx.y * 64;
    const int n0 = blockIdx.x * 64;
    const int tid = threadIdx.x;
    const int tx = tid & 15, ty = tid >> 4;
    float acc[4][4];
#pragma unroll
    for (int i = 0; i < 4; i++)
#pragma unroll
        for (int j = 0; j < 4; j++) acc[i][j] = 0.f;

    for (int k0 = 0; k0 < NF; k0 += 16) {
#pragma unroll
        for (int i = 0; i < 4; ++i) {
            int e = tid + i * 256;
            int kk = e & 15, row = e >> 4;
            As[kk][row] = g_ctx[(size_t)(m0 + row) * NF + k0 + kk];
        }
#pragma unroll
        for (int i = 0; i < 4; ++i) {
            int e = tid + i * 256;
            int col = e & 63, kk = e >> 6;
            Bs[kk][col] = W[(size_t)(k0 + kk) * NF + n0 + col];
        }
        __syncthreads();
#pragma unroll
        for (int kk = 0; kk < 16; ++kk) {
            float a[4], bv[4];
#pragma unroll
            for (int i = 0; i < 4; i++) a[i] = As[kk][ty * 4 + i];
#pragma unroll
            for (int j = 0; j < 4; j++) bv[j] = Bs[kk][tx * 4 + j];
#pragma unroll
            for (int i = 0; i < 4; i++)
#pragma unroll
                for (int j = 0; j < 4; j++) acc[i][j] += a[i] * bv[j];
        }
        __syncthreads();
    }
#pragma unroll
    for (int i = 0; i < 4; i++) {
        int m = m0 + ty * 4 + i;
#pragma unroll
        for (int j = 0; j < 4; j++) {
            int n = n0 + tx * 4 + j;
            out[(size_t)m * NF + n] =
                acc[i][j] + bias[n] + g_fsmn[(size_t)m * NF + n];
        }
    }
}

// ---------------------------------------------------------------------------
extern "C" void kernel_launch(void* const* d_in, const int* in_sizes, int n_in,
                              void* d_out, int out_size) {
    const float* x      = (const float*)d_in[0];
    const float* mask   = (const float*)d_in[1];
    const float* w_qkv  = (const float*)d_in[2];
    const float* b_qkv  = (const float*)d_in[3];
    const float* w_out  = (const float*)d_in[4];
    const float* b_out  = (const float*)d_in[5];
    const float* w_fsmn = (const float*)d_in[6];
    float* out = (float*)d_out;

    k_gemm_qkv<<<dim3(QKV_LD / 64, BB * TT / 64), 256>>>(x, w_qkv, b_qkv);
    k_fsmn<<<BB * TT, NF>>>(mask, w_fsmn);
    k_gemm_scores<<<dim3(TT / 64, TT / 64, BB * NH), 256>>>(mask);
    k_softmax<<<BB * NH * TT, 256>>>();
    k_gemm_pv<<<dim3(DK / 64, TT / 64, BB * NH), 256>>>();
    k_gemm_out<<<dim3(NF / 64, BB * TT / 64), 256>>>(w_out, b_out, out);
}

// round 2
// speedup vs baseline: 1.4828x; 1.4828x over previous
#include <cuda_runtime.h>
#include <math.h>
#include <stdint.h>

#define BB 16
#define TT 1024
#define CIN 512
#define NF 512
#define NH 4
#define DK 128
#define QKV_LD 1536
#define KER 11
#define LPAD 5
#define NEGV (-1.0e9f)
#define SCALE 0.08838834764831845f  // 128^-0.5

// Scratch (static device globals; no runtime allocation)
static __device__ float g_qkv[(size_t)BB * TT * QKV_LD];          // 100 MB
static __device__ float g_scores[(size_t)BB * NH * TT * TT];      // 256 MB
static __device__ float g_ctx[(size_t)BB * TT * NF];              // 33.5 MB
static __device__ float g_fsmn[(size_t)BB * TT * NF];             // 33.5 MB

// ---------------------------------------------------------------------------
// tf32 helpers
// ---------------------------------------------------------------------------
__device__ __forceinline__ uint32_t f2tf(float f) {
    uint32_t u;
    asm("cvt.rna.tf32.f32 %0, %1;" : "=r"(u) : "f"(f));
    return u;
}

__device__ __forceinline__ void mma_tf32(float acc[4],
                                         const uint32_t a[4],
                                         const uint32_t b[2]) {
    asm volatile(
        "mma.sync.aligned.m16n8k8.row.col.f32.tf32.tf32.f32 "
        "{%0,%1,%2,%3}, {%4,%5,%6,%7}, {%8,%9}, {%0,%1,%2,%3};"
        : "+f"(acc[0]), "+f"(acc[1]), "+f"(acc[2]), "+f"(acc[3])
        : "r"(a[0]), "r"(a[1]), "r"(a[2]), "r"(a[3]), "r"(b[0]), "r"(b[1]));
}

// ---------------------------------------------------------------------------
// Core 128x128xK GEMM on tensor cores (tf32), 256 threads = 8 warps (2m x 4n),
// each warp computes 64x32 via m16n8k8 fragments.
// Fragment-ordered smem: scattered 4B STS once, vectorized LDS.128/.64 reads.
// If BNK: B element (k,n) is read from B[n*ldb + k]; else B[k*ldb + n].
// ---------------------------------------------------------------------------
template <bool BNK>
__device__ __forceinline__ void gemm_mma_core(
    const float* __restrict__ A, size_t lda,
    const float* __restrict__ B, size_t ldb,
    int m0, int n0, int K, float acc[4][4][4],
    uint32_t* as, uint32_t* bs)
{
    const int tid = threadIdx.x;
    const int lane = tid & 31;
    const int warp = tid >> 5;
    const int wm = warp >> 2;   // 0..1
    const int wn = warp & 3;    // 0..3

    for (int k0 = 0; k0 < K; k0 += 16) {
        // ---- stage A tile (128 x 16) into fragment order ----
#pragma unroll
        for (int i = 0; i < 2; i++) {
            int e = tid + i * 256;          // 0..511 float4s
            int m = e >> 2, kq = e & 3;
            float4 v = *(const float4*)(A + (size_t)(m0 + m) * lda + k0 + kq * 4);
            float vv[4] = {v.x, v.y, v.z, v.w};
#pragma unroll
            for (int j = 0; j < 4; j++) {
                int k = kq * 4 + j;
                int frag = (m >> 4) * 2 + (k >> 3);
                int l = (m & 7) * 4 + (k & 3);
                int r = ((m >> 3) & 1) + ((k >> 2) & 1) * 2;
                as[frag * 128 + l * 4 + r] = f2tf(vv[j]);
            }
        }
        // ---- stage B tile (16 x 128) into fragment order ----
#pragma unroll
        for (int i = 0; i < 2; i++) {
            int e = tid + i * 256;
            if (BNK) {
                int n = e >> 2, kq = e & 3;
                float4 v = *(const float4*)(B + (size_t)(n0 + n) * ldb + k0 + kq * 4);
                float vv[4] = {v.x, v.y, v.z, v.w};
#pragma unroll
                for (int j = 0; j < 4; j++) {
                    int k = kq * 4 + j;
                    int idx = ((n >> 3) * 2 + (k >> 3)) * 64 +
                              ((n & 7) * 4 + (k & 3)) * 2 + ((k >> 2) & 1);
                    bs[idx] = f2tf(vv[j]);
                }
            } else {
                int k = e >> 5, nq = e & 31;
                float4 v = *(const float4*)(B + (size_t)(k0 + k) * ldb + n0 + nq * 4);
                float vv[4] = {v.x, v.y, v.z, v.w};
#pragma unroll
                for (int j = 0; j < 4; j++) {
                    int n = nq * 4 + j;
                    int idx = ((n >> 3) * 2 + (k >> 3)) * 64 +
                              ((n & 7) * 4 + (k & 3)) * 2 + ((k >> 2) & 1);
                    bs[idx] = f2tf(vv[j]);
                }
            }
        }
        __syncthreads();
        // ---- compute: 2 k-steps of m16n8k8 over 4 m-tiles x 4 n-tiles ----
#pragma unroll
        for (int ks = 0; ks < 2; ks++) {
            uint32_t a[4][4], b[4][2];
#pragma unroll
            for (int mt = 0; mt < 4; mt++) {
                const uint4 p = *(const uint4*)(as + ((wm * 4 + mt) * 2 + ks) * 128 + lane * 4);
                a[mt][0] = p.x; a[mt][1] = p.y; a[mt][2] = p.z; a[mt][3] = p.w;
            }
#pragma unroll
            for (int nt = 0; nt < 4; nt++) {
                const uint2 p = *(const uint2*)(bs + ((wn * 4 + nt) * 2 + ks) * 64 + lane * 2);
                b[nt][0] = p.x; b[nt][1] = p.y;
            }
#pragma unroll
            for (int mt = 0; mt < 4; mt++)
#pragma unroll
                for (int nt = 0; nt < 4; nt++)
                    mma_tf32(acc[mt][nt], a[mt], b[nt]);
        }
        __syncthreads();
    }
}

// Epilogue index helpers: logical (row,col) within the 128x128 block per acc reg
#define EPI_ROW(wm, mt, lane, cr) ((wm) * 64 + (mt) * 16 + ((lane) >> 2) + (((cr) & 2) ? 8 : 0))
#define EPI_COL(wn, nt, lane, cr) ((wn) * 32 + (nt) * 8 + ((lane) & 3) * 2 + ((cr) & 1))

// ---------------------------------------------------------------------------
// GEMM 1: qkv = X @ Wqkv + b_qkv         (M=16384, N=1536, K=512)
// ---------------------------------------------------------------------------
__global__ __launch_bounds__(256) void k_gemm_qkv(const float* __restrict__ X,
                                                  const float* __restrict__ W,
                                                  const float* __restrict__ bias) {
    __shared__ uint32_t as[2048], bs[2048];
    const int m0 = blockIdx.y * 128, n0 = blockIdx.x * 128;
    const int lane = threadIdx.x & 31, warp = threadIdx.x >> 5;
    const int wm = warp >> 2, wn = warp & 3;
    float acc[4][4][4] = {};
    gemm_mma_core<false>(X, CIN, W, QKV_LD, m0, n0, CIN, acc, as, bs);
#pragma unroll
    for (int mt = 0; mt < 4; mt++)
#pragma unroll
        for (int nt = 0; nt < 4; nt++)
#pragma unroll
            for (int cr = 0; cr < 4; cr++) {
                int m = m0 + EPI_ROW(wm, mt, lane, cr);
                int n = n0 + EPI_COL(wn, nt, lane, cr);
                g_qkv[(size_t)m * QKV_LD + n] = acc[mt][nt][cr] + bias[n];
            }
}

// ---------------------------------------------------------------------------
// FSMN: depthwise conv (k=11) over masked V + residual, re-masked.
// ---------------------------------------------------------------------------
__global__ void k_fsmn(const float* __restrict__ mask,
                       const float* __restrict__ w_fsmn) {
    const int bt = blockIdx.x;
    const int b = bt >> 10;
    const int t = bt & (TT - 1);
    const int d = threadIdx.x;
    const float m = mask[b * TT + t];
    const float* vbase = g_qkv + (size_t)b * TT * QKV_LD + 2 * NF + d;
    float acc = vbase[(size_t)t * QKV_LD] * m;   // residual
#pragma unroll
    for (int j = 0; j < KER; ++j) {
        int tt = t + j - LPAD;
        if (tt >= 0 && tt < TT) {
            float mm = mask[b * TT + tt];
            acc += w_fsmn[d * KER + j] * vbase[(size_t)tt * QKV_LD] * mm;
        }
    }
    g_fsmn[(size_t)bt * NF + d] = acc * m;
}

// ---------------------------------------------------------------------------
// GEMM 2: scores = (Q*scale) @ K^T, key mask -> -1e9   (per b,h: 1024x1024x128)
// ---------------------------------------------------------------------------
__global__ __launch_bounds__(256) void k_gemm_scores(const float* __restrict__ mask) {
    __shared__ uint32_t as[2048], bs[2048];
    const int bh = blockIdx.z;
    const int b = bh >> 2, h = bh & 3;
    const float* Q = g_qkv + (size_t)b * TT * QKV_LD + h * DK;
    const float* Kp = g_qkv + (size_t)b * TT * QKV_LD + NF + h * DK;
    float* S = g_scores + (size_t)bh * TT * TT;
    const int m0 = blockIdx.y * 128, n0 = blockIdx.x * 128;
    const int lane = threadIdx.x & 31, warp = threadIdx.x >> 5;
    const int wm = warp >> 2, wn = warp & 3;
    float acc[4][4][4] = {};
    gemm_mma_core<true>(Q, QKV_LD, Kp, QKV_LD, m0, n0, DK, acc, as, bs);
#pragma unroll
    for (int mt = 0; mt < 4; mt++)
#pragma unroll
        for (int nt = 0; nt < 4; nt++)
#pragma unroll
            for (int cr = 0; cr < 4; cr++) {
                int m = m0 + EPI_ROW(wm, mt, lane, cr);
                int n = n0 + EPI_COL(wn, nt, lane, cr);
                float mv = mask[b * TT + n];
                S[(size_t)m * TT + n] = (mv != 0.f) ? acc[mt][nt][cr] * SCALE : NEGV;
            }
}

// ---------------------------------------------------------------------------
// Row softmax over 1024 keys.
// ---------------------------------------------------------------------------
__global__ void k_softmax() {
    float* S = g_scores + (size_t)blockIdx.x * TT;
    const int tid = threadIdx.x;
    float v[4];
    float mx = -INFINITY;
#pragma unroll
    for (int i = 0; i < 4; i++) {
        v[i] = S[tid + i * 256];
        mx = fmaxf(mx, v[i]);
    }
    __shared__ float shm[8], shs[8];
#pragma unroll
    for (int o = 16; o > 0; o >>= 1) mx = fmaxf(mx, __shfl_xor_sync(0xffffffffu, mx, o));
    if ((tid & 31) == 0) shm[tid >> 5] = mx;
    __syncthreads();
    if (tid == 0) {
        float t = shm[0];
        for (int w = 1; w < 8; w++) t = fmaxf(t, shm[w]);
        shm[0] = t;
    }
    __syncthreads();
    const float bm = shm[0];
    float s = 0.f;
#pragma unroll
    for (int i = 0; i < 4; i++) {
        v[i] = __expf(v[i] - bm);
        s += v[i];
    }
#pragma unroll
    for (int o = 16; o > 0; o >>= 1) s += __shfl_xor_sync(0xffffffffu, s, o);
    if ((tid & 31) == 0) shs[tid >> 5] = s;
    __syncthreads();
    if (tid == 0) {
        float t = 0.f;
        for (int w = 0; w < 8; w++) t += shs[w];
        shs[0] = t;
    }
    __syncthreads();
    const float inv = 1.f / shs[0];
#pragma unroll
    for (int i = 0; i < 4; i++) S[tid + i * 256] = v[i] * inv;
}

// ---------------------------------------------------------------------------
// GEMM 3: ctx = P @ V                    (per b,h: 1024x128x1024)
// ---------------------------------------------------------------------------
__global__ __launch_bounds__(256) void k_gemm_pv() {
    __shared__ uint32_t as[2048], bs[2048];
    const int bh = blockIdx.z;
    const int b = bh >> 2, h = bh & 3;
    const float* P = g_scores + (size_t)bh * TT * TT;
    const float* V = g_qkv + (size_t)b * TT * QKV_LD + 2 * NF + h * DK;
    const int m0 = blockIdx.y * 128, n0 = blockIdx.x * 128;  // n0 == 0 (N=128)
    const int lane = threadIdx.x & 31, warp = threadIdx.x >> 5;
    const int wm = warp >> 2, wn = warp & 3;
    float acc[4][4][4] = {};
    gemm_mma_core<false>(P, TT, V, QKV_LD, m0, n0, TT, acc, as, bs);
#pragma unroll
    for (int mt = 0; mt < 4; mt++)
#pragma unroll
        for (int nt = 0; nt < 4; nt++)
#pragma unroll
            for (int cr = 0; cr < 4; cr++) {
                int m = m0 + EPI_ROW(wm, mt, lane, cr);
                int n = n0 + EPI_COL(wn, nt, lane, cr);
                g_ctx[((size_t)b * TT + m) * NF + h * DK + n] = acc[mt][nt][cr];
            }
}

// ---------------------------------------------------------------------------
// GEMM 4: out = ctx @ w_out + b_out + fsmn   (M=16384, N=512, K=512)
// ---------------------------------------------------------------------------
__global__ __launch_bounds__(256) void k_gemm_out(const float* __restrict__ W,
                                                  const float* __restrict__ bias,
                                                  float* __restrict__ out) {
    __shared__ uint32_t as[2048], bs[2048];
    const int m0 = blockIdx.y * 128, n0 = blockIdx.x * 128;
    const int lane = threadIdx.x & 31, warp = threadIdx.x >> 5;
    const int wm = warp >> 2, wn = warp & 3;
    float acc[4][4][4] = {};
    gemm_mma_core<false>(g_ctx, NF, W, NF, m0, n0, NF, acc, as, bs);
#pragma unroll
    for (int mt = 0; mt < 4; mt++)
#pragma unroll
        for (int nt = 0; nt < 4; nt++)
#pragma unroll
            for (int cr = 0; cr < 4; cr++) {
                int m = m0 + EPI_ROW(wm, mt, lane, cr);
                int n = n0 + EPI_COL(wn, nt, lane, cr);
                out[(size_t)m * NF + n] =
                    acc[mt][nt][cr] + bias[n] + g_fsmn[(size_t)m * NF + n];
            }
}

// ---------------------------------------------------------------------------
extern "C" void kernel_launch(void* const* d_in, const int* in_sizes, int n_in,
                              void* d_out, int out_size) {
    const float* x      = (const float*)d_in[0];
    const float* mask   = (const float*)d_in[1];
    const float* w_qkv  = (const float*)d_in[2];
    const float* b_qkv  = (const float*)d_in[3];
    const float* w_out  = (const float*)d_in[4];
    const float* b_out  = (const float*)d_in[5];
    const float* w_fsmn = (const float*)d_in[6];
    float* out = (float*)d_out;

    k_gemm_qkv<<<dim3(QKV_LD / 128, BB * TT / 128), 256>>>(x, w_qkv, b_qkv);
    k_fsmn<<<BB * TT, NF>>>(mask, w_fsmn);
    k_gemm_scores<<<dim3(TT / 128, TT / 128, BB * NH), 256>>>(mask);
    k_softmax<<<BB * NH * TT, 256>>>();
    k_gemm_pv<<<dim3(DK / 128, TT / 128, BB * NH), 256>>>();
    k_gemm_out<<<dim3(NF / 128, BB * TT / 128), 256>>>(w_out, b_out, out);
}